// round 9
// baseline (speedup 1.0000x reference)
#include <cuda_runtime.h>
#include <math.h>

#define Bdim 4
#define Sdim 512
#define Kdim 32
#define Vdim 32000
#define ROWS (Bdim * Sdim)   /* 2048 */
#define NTHREADS 256
#define V4 (Vdim / 4)        /* 8000 */
#define CAND_CAP 1024

__device__ __forceinline__ float warp_sum(float v) {
#pragma unroll
    for (int o = 16; o > 0; o >>= 1) v += __shfl_xor_sync(0xffffffffu, v, o);
    return v;
}
__device__ __forceinline__ float warp_max(float v) {
#pragma unroll
    for (int o = 16; o > 0; o >>= 1) v = fmaxf(v, __shfl_xor_sync(0xffffffffu, v, o));
    return v;
}
// fallback-only: insert into descending 8-list
__device__ __forceinline__ void ins8(float (&t)[8], float v) {
    if (v <= t[7]) return;
    t[7] = v;
#pragma unroll
    for (int i = 7; i > 0; --i)
        if (t[i] > t[i - 1]) { float tmp = t[i - 1]; t[i - 1] = t[i]; t[i] = tmp; }
}

__global__ __launch_bounds__(NTHREADS)
void robust_combiner_kernel(const int*   __restrict__ tgt,
                            const float* __restrict__ dists,
                            const float* __restrict__ keyf,
                            const float* __restrict__ nprobs,
                            const float* __restrict__ selp,
                            const float* __restrict__ Wf,  const float* __restrict__ bf,
                            const float* __restrict__ W1a, const float* __restrict__ b1a,
                            const float* __restrict__ W1b, const float* __restrict__ b1b,
                            const float* __restrict__ W2a, const float* __restrict__ b2a,
                            const float* __restrict__ W2b, const float* __restrict__ b2b,
                            float* __restrict__ out)
{
    const int row = blockIdx.x;
    const int tid = threadIdx.x;

    __shared__ float s_max[NTHREADS];
    __shared__ float s_cand[CAND_CAP];
    __shared__ int   s_cnt_c;
    __shared__ float s_T;
    __shared__ float s_top8[8];
    __shared__ float s_d[Kdim], s_lk[Kdim], s_ls[Kdim], s_cnt[Kdim], s_p[Kdim];
    __shared__ int   s_t[Kdim];

    const float4* __restrict__ in4  = reinterpret_cast<const float4*>(nprobs) + (size_t)row * V4;
    float4*       __restrict__ out4 = reinterpret_cast<float4*>(out)          + (size_t)row * V4;
    const float4 z4 = make_float4(0.f, 0.f, 0.f, 0.f);

    if (tid == 0) s_cnt_c = 0;

    // ---- Phase 0: subset threshold from the first 1024 values (16 KB) ----
    {
        float4 v = in4[tid];                       // tid < 256 <= V4; stays L1-hot
        s_max[tid] = fmaxf(fmaxf(v.x, v.y), fmaxf(v.z, v.w));
    }
    __syncthreads();

    // T = 8th-largest of the 256 thread maxima (a 256-element subset of the row,
    // so >= 8 row elements are >= T -> all global top-8 are >= T).
    // Ballot-elected single-winner removal (tie-safe).
    if (tid < 32) {
        float m8[8];
#pragma unroll
        for (int j = 0; j < 8; j++) m8[j] = s_max[tid + 32 * j];
        float T = 0.f;
#pragma unroll
        for (int r = 0; r < 8; r++) {
            float lv = m8[0]; int lj = 0;
#pragma unroll
            for (int j = 1; j < 8; j++) if (m8[j] > lv) { lv = m8[j]; lj = j; }
            float mv = warp_max(lv);
            unsigned ball = __ballot_sync(0xffffffffu, lv == mv);
            int wl = __ffs(ball) - 1;              // exactly one winner, even on ties
            if (tid == wl) m8[lj] = -INFINITY;
            T = mv;
        }
        if (tid == 0) s_T = T;
    }
    __syncthreads();

    // ---- Main pass: SINGLE full DRAM read + zero-fill + candidate collection ----
    const float T = s_T;
#pragma unroll 4
    for (int i = tid; i < V4; i += NTHREADS) {
        float4 v = __ldcs(&in4[i]);                // streaming: no reuse
        __stcs(&out4[i], z4);                      // streaming zero-fill
        if (fmaxf(fmaxf(v.x, v.y), fmaxf(v.z, v.w)) >= T) {   // ~250/8000 hit rate
            if (v.x >= T) { int p = atomicAdd(&s_cnt_c, 1); if (p < CAND_CAP) s_cand[p] = v.x; }
            if (v.y >= T) { int p = atomicAdd(&s_cnt_c, 1); if (p < CAND_CAP) s_cand[p] = v.y; }
            if (v.z >= T) { int p = atomicAdd(&s_cnt_c, 1); if (p < CAND_CAP) s_cand[p] = v.z; }
            if (v.w >= T) { int p = atomicAdd(&s_cnt_c, 1); if (p < CAND_CAP) s_cand[p] = v.w; }
        }
    }
    __syncthreads();

    // ---- Exact top-8 from candidates (warp 0); serial fallback on overflow ----
    if (tid < 32) {
        int cnt = s_cnt_c;
        if (cnt <= CAND_CAP) {                     // normal path; cnt >= 8 guaranteed
            int per = (cnt + 31) / 32;             // disjoint lane subsets
#pragma unroll 1
            for (int r = 0; r < 8; r++) {
                float lv = -INFINITY; int li = 0;
                for (int e = 0; e < per; e++) {
                    int idx = tid + 32 * e;
                    if (idx < cnt) { float c = s_cand[idx]; if (c > lv) { lv = c; li = idx; } }
                }
                float mv = warp_max(lv);
                unsigned ball = __ballot_sync(0xffffffffu, lv == mv);
                int wl = __ffs(ball) - 1;          // one removal per round; ties land
                if (tid == wl) s_cand[li] = -INFINITY;  // in consecutive rounds (= top_k)
                if (tid == 0) s_top8[r] = mv;
            }
        } else if (tid == 0) {                     // overflow fallback: serial exact scan
            float t8[8];
#pragma unroll
            for (int j = 0; j < 8; j++) t8[j] = -1.0f;
            const float* rowp = nprobs + (size_t)row * Vdim;
            for (int i = 0; i < Vdim; i++) ins8(t8, rowp[i]);
#pragma unroll
            for (int j = 0; j < 8; j++) s_top8[j] = t8[j];
        }
    }
    __syncthreads();

    // ---- Phase C: per-row scalar math on warp 0 (one lane per k) ----
    if (tid < Kdim) {
        const int k = tid;
        const size_t base = (size_t)row * Kdim;

        int   tv = tgt[base + k];
        float d  = dists[base + k];
        float lk = logf(keyf[base + k]);
        float ls = logf(selp[base + k]);
        s_t[k] = tv; s_d[k] = d; s_lk[k] = lk; s_ls[k] = ls;

        // noise_logit: Linear(2->4) -> tanh -> Linear(4->1)
        float nz = b1b[0];
#pragma unroll
        for (int i = 0; i < 4; i++) {
            float h = tanhf(W1a[2 * i] * lk + W1a[2 * i + 1] * ls + b1a[i]);
            nz += W1b[i] * h;
        }
        __syncwarp();

        // label_counts[k]: distinct NONZERO labels in prefix [0..k]
        int cnt = 0;
        for (int i = 0; i <= k; i++) {
            int vi = s_t[i];
            if (vi == 0) continue;
            bool dup = false;
            for (int j = 0; j < i; j++) if (s_t[j] == vi) { dup = true; break; }
            if (!dup) cnt++;
        }
        s_cnt[k] = (float)cnt;
        __syncwarp();

        // fc2 hidden unit k: tanh(W2a[k] . [dists(32), counts(32)] + b2a[k])
        float acc = b2a[k];
        const float* wrow = W2a + k * (2 * Kdim);
#pragma unroll
        for (int i = 0; i < Kdim; i++) acc += wrow[i] * s_d[i];
#pragma unroll
        for (int i = 0; i < Kdim; i++) acc += wrow[Kdim + i] * s_cnt[i];
        float h = tanhf(acc);

        // lambda_logit = W2b @ h + b2b
        float l0 = warp_sum(W2b[k] * h)        + b2b[0];
        float l1 = warp_sum(W2b[Kdim + k] * h) + b2b[1];

        // sim_lambda = W_func . [log(top8)(8), log_key(32), log_sel(32)] + b_func
        float part = Wf[8 + k] * lk + Wf[40 + k] * ls;
        if (k < 8) part += Wf[k] * logf(s_top8[k]);
        float sim = warp_sum(part) + bf[0];

        float lam   = 1.0f / (1.0f + expf(sim - l0));   // softmax([l0,sim])[0]
        float tempe = 1.0f / (1.0f + expf(-l1));        // sigmoid(l1)

        // probs = softmax(-dists*tempe + noise) over K
        float logit = -d * tempe + nz;
        float mx = warp_max(logit);
        float e  = expf(logit - mx);
        float se = warp_sum(e);
        s_p[k] = e / se;
        __syncwarp();

        if (k == 0) {
            out[(size_t)Vdim * ROWS + row] = lam;
            float* orow = out + (size_t)row * Vdim;
            for (int i = 0; i < Kdim; i++) orow[s_t[i]] = s_p[i];  // last-write-wins
        }
    }
}

extern "C" void kernel_launch(void* const* d_in, const int* in_sizes, int n_in,
                              void* d_out, int out_size) {
    const int*   tgt    = (const int*)  d_in[0];
    const float* dists  = (const float*)d_in[1];
    const float* keyf   = (const float*)d_in[2];
    const float* nprobs = (const float*)d_in[3];
    const float* selp   = (const float*)d_in[4];
    const float* Wf     = (const float*)d_in[5];
    const float* bf     = (const float*)d_in[6];
    const float* W1a    = (const float*)d_in[7];
    const float* b1a    = (const float*)d_in[8];
    const float* W1b    = (const float*)d_in[9];
    const float* b1b    = (const float*)d_in[10];
    const float* W2a    = (const float*)d_in[11];
    const float* b2a    = (const float*)d_in[12];
    const float* W2b    = (const float*)d_in[13];
    const float* b2b    = (const float*)d_in[14];
    float* out = (float*)d_out;

    robust_combiner_kernel<<<ROWS, NTHREADS>>>(
        tgt, dists, keyf, nprobs, selp,
        Wf, bf, W1a, b1a, W1b, b1b, W2a, b2a, W2b, b2b, out);
}

// round 10
// speedup vs baseline: 1.7178x; 1.7178x over previous
#include <cuda_runtime.h>
#include <math.h>

#define Bdim 4
#define Sdim 512
#define Kdim 32
#define Vdim 32000
#define ROWS (Bdim * Sdim)   /* 2048 */
#define NTHREADS 256
#define V4 (Vdim / 4)        /* 8000 */
#define CAND_CAP 1024
#define BATCH_END 7168       /* 7 * NTHREADS * 4; tail = 832 float4s */

__device__ __forceinline__ float warp_sum(float v) {
#pragma unroll
    for (int o = 16; o > 0; o >>= 1) v += __shfl_xor_sync(0xffffffffu, v, o);
    return v;
}
__device__ __forceinline__ float warp_max(float v) {
#pragma unroll
    for (int o = 16; o > 0; o >>= 1) v = fmaxf(v, __shfl_xor_sync(0xffffffffu, v, o));
    return v;
}
__device__ __forceinline__ float max4(float4 v) {
    return fmaxf(fmaxf(v.x, v.y), fmaxf(v.z, v.w));
}
// fallback-only: insert into descending 8-list
__device__ __forceinline__ void ins8(float (&t)[8], float v) {
    if (v <= t[7]) return;
    t[7] = v;
#pragma unroll
    for (int i = 7; i > 0; --i)
        if (t[i] > t[i - 1]) { float tmp = t[i - 1]; t[i - 1] = t[i]; t[i] = tmp; }
}
// rare hit path: ONE atomic per hit lane, then sequential stores
__device__ __forceinline__ void collect(float4 v, float T, float* s_cand, int* s_cnt_c) {
    int n = (v.x >= T) + (v.y >= T) + (v.z >= T) + (v.w >= T);
    int p = atomicAdd(s_cnt_c, n);
    if (v.x >= T) { if (p < CAND_CAP) s_cand[p] = v.x; p++; }
    if (v.y >= T) { if (p < CAND_CAP) s_cand[p] = v.y; p++; }
    if (v.z >= T) { if (p < CAND_CAP) s_cand[p] = v.z; p++; }
    if (v.w >= T) { if (p < CAND_CAP) s_cand[p] = v.w; p++; }
}

__global__ __launch_bounds__(NTHREADS)
void robust_combiner_kernel(const int*   __restrict__ tgt,
                            const float* __restrict__ dists,
                            const float* __restrict__ keyf,
                            const float* __restrict__ nprobs,
                            const float* __restrict__ selp,
                            const float* __restrict__ Wf,  const float* __restrict__ bf,
                            const float* __restrict__ W1a, const float* __restrict__ b1a,
                            const float* __restrict__ W1b, const float* __restrict__ b1b,
                            const float* __restrict__ W2a, const float* __restrict__ b2a,
                            const float* __restrict__ W2b, const float* __restrict__ b2b,
                            float* __restrict__ out)
{
    const int row = blockIdx.x;
    const int tid = threadIdx.x;

    __shared__ float s_max[NTHREADS];
    __shared__ float s_cand[CAND_CAP];
    __shared__ int   s_cnt_c;
    __shared__ float s_T;
    __shared__ float s_top8[8];
    __shared__ float s_d[Kdim], s_lk[Kdim], s_ls[Kdim], s_cnt[Kdim], s_p[Kdim];
    __shared__ int   s_t[Kdim];

    const float4* __restrict__ in4  = reinterpret_cast<const float4*>(nprobs) + (size_t)row * V4;
    float4*       __restrict__ out4 = reinterpret_cast<float4*>(out)          + (size_t)row * V4;
    const float4 z4 = make_float4(0.f, 0.f, 0.f, 0.f);
    const size_t kbase = (size_t)row * Kdim;

    if (tid == 0) s_cnt_c = 0;

    // ---- Phase 0: 2048-element subset sample (2 float4 / thread, L2-hot re-read later) ----
    {
        float4 a = in4[tid];
        float4 b = in4[tid + NTHREADS];
        s_max[tid] = fmaxf(max4(a), max4(b));
    }
    __syncthreads();

    // ---- Concurrent: warp 0 threshold; warps 1-4 prefetch phase-C inputs ----
    if (tid < 32) {
        // T = 8th-largest of 256 thread maxima (each a real row element >= T
        // -> >= 8 row elements >= T -> all global top-8 >= T, cnt >= 8).
        float m = s_max[tid];
        float T = 0.f;
#pragma unroll
        for (int r = 0; r < 8; r++) {
            float lv = fmaxf(fmaxf(m, s_max[tid + 32]),
                       fmaxf(fmaxf(s_max[tid + 64], s_max[tid + 96]),
                       fmaxf(fmaxf(s_max[tid + 128], s_max[tid + 160]),
                             fmaxf(s_max[tid + 192], s_max[tid + 224]))));
            // NOTE: need per-lane 8-way max with removal -> keep register copy
            lv = lv; // placeholder removed below
            break;
        }
        // (re-done properly below)
        float m8[8];
#pragma unroll
        for (int j = 0; j < 8; j++) m8[j] = s_max[tid + 32 * j];
#pragma unroll
        for (int r = 0; r < 8; r++) {
            float lv = m8[0]; int lj = 0;
#pragma unroll
            for (int j = 1; j < 8; j++) if (m8[j] > lv) { lv = m8[j]; lj = j; }
            float mv = warp_max(lv);
            unsigned ball = __ballot_sync(0xffffffffu, lv == mv);
            int wl = __ffs(ball) - 1;              // exactly one winner, even on ties
            if (tid == wl) m8[lj] = -INFINITY;
            T = mv;
        }
        if (tid == 0) s_T = T;
    } else if (tid < 64) {
        int j = tid - 32;  s_t[j]  = tgt[kbase + j];
    } else if (tid < 96) {
        int j = tid - 64;  s_d[j]  = dists[kbase + j];
    } else if (tid < 128) {
        int j = tid - 96;  s_lk[j] = logf(keyf[kbase + j]);
    } else if (tid < 160) {
        int j = tid - 128; s_ls[j] = logf(selp[kbase + j]);
    }
    __syncthreads();

    // ---- Main pass: single full DRAM read + zero-fill + rare candidate hits ----
    const float T = s_T;
    for (int base = tid; base < BATCH_END; base += NTHREADS * 4) {
        // 4 loads issued back-to-back (MLP=4), then 4 stores, then cheap checks
        float4 v0 = __ldcs(&in4[base]);
        float4 v1 = __ldcs(&in4[base +     NTHREADS]);
        float4 v2 = __ldcs(&in4[base + 2 * NTHREADS]);
        float4 v3 = __ldcs(&in4[base + 3 * NTHREADS]);
        __stcs(&out4[base],                z4);
        __stcs(&out4[base +     NTHREADS], z4);
        __stcs(&out4[base + 2 * NTHREADS], z4);
        __stcs(&out4[base + 3 * NTHREADS], z4);
        if (max4(v0) >= T) collect(v0, T, s_cand, &s_cnt_c);
        if (max4(v1) >= T) collect(v1, T, s_cand, &s_cnt_c);
        if (max4(v2) >= T) collect(v2, T, s_cand, &s_cnt_c);
        if (max4(v3) >= T) collect(v3, T, s_cand, &s_cnt_c);
    }
    for (int i = BATCH_END + tid; i < V4; i += NTHREADS) {   // tail: 832 float4s
        float4 v = __ldcs(&in4[i]);
        __stcs(&out4[i], z4);
        if (max4(v) >= T) collect(v, T, s_cand, &s_cnt_c);
    }
    __syncthreads();

    // ---- Exact top-8 from candidates (warp 0); serial fallback on overflow ----
    if (tid < 32) {
        int cnt = s_cnt_c;
        if (cnt <= CAND_CAP) {                     // normal path; cnt >= 8 guaranteed
            int per = (cnt + 31) / 32;             // disjoint lane subsets
#pragma unroll 1
            for (int r = 0; r < 8; r++) {
                float lv = -INFINITY; int li = 0;
                for (int e = 0; e < per; e++) {
                    int idx = tid + 32 * e;
                    if (idx < cnt) { float c = s_cand[idx]; if (c > lv) { lv = c; li = idx; } }
                }
                float mv = warp_max(lv);
                unsigned ball = __ballot_sync(0xffffffffu, lv == mv);
                int wl = __ffs(ball) - 1;          // one removal/round; ties land in
                if (tid == wl) s_cand[li] = -INFINITY;  // consecutive rounds (= top_k)
                if (tid == 0) s_top8[r] = mv;
            }
        } else if (tid == 0) {                     // overflow fallback: serial exact
            float t8[8];
#pragma unroll
            for (int j = 0; j < 8; j++) t8[j] = -1.0f;
            const float* rowp = nprobs + (size_t)row * Vdim;
            for (int i = 0; i < Vdim; i++) ins8(t8, rowp[i]);
#pragma unroll
            for (int j = 0; j < 8; j++) s_top8[j] = t8[j];
        }
    }
    __syncthreads();

    // ---- Phase C: per-row scalar math on warp 0 (one lane per k), inputs smem-hot ----
    if (tid < Kdim) {
        const int k = tid;
        int   tv = s_t[k];
        float d  = s_d[k];
        float lk = s_lk[k];
        float ls = s_ls[k];

        // noise_logit: Linear(2->4) -> tanh -> Linear(4->1)
        float nz = b1b[0];
#pragma unroll
        for (int i = 0; i < 4; i++) {
            float h = tanhf(W1a[2 * i] * lk + W1a[2 * i + 1] * ls + b1a[i]);
            nz += W1b[i] * h;
        }

        // label_counts[k] = # distinct NONZERO labels in prefix [0..k]
        // contrib[i] = (label!=0 && first occurrence); inclusive prefix via ballot+popc
        bool dup = false;
        for (int j = 0; j < k; j++) dup |= (s_t[j] == tv);
        int contrib = (tv != 0) && !dup;
        unsigned ball = __ballot_sync(0xffffffffu, contrib);
        unsigned lemask = 0xffffffffu >> (31 - k);
        s_cnt[k] = (float)__popc(ball & lemask);
        __syncwarp();

        // fc2 hidden unit k: tanh(W2a[k] . [dists(32), counts(32)] + b2a[k])
        float acc = b2a[k];
        const float* wrow = W2a + k * (2 * Kdim);
#pragma unroll
        for (int i = 0; i < Kdim; i++) acc += wrow[i] * s_d[i];
#pragma unroll
        for (int i = 0; i < Kdim; i++) acc += wrow[Kdim + i] * s_cnt[i];
        float h = tanhf(acc);

        // lambda_logit = W2b @ h + b2b
        float l0 = warp_sum(W2b[k] * h)        + b2b[0];
        float l1 = warp_sum(W2b[Kdim + k] * h) + b2b[1];

        // sim_lambda = W_func . [log(top8)(8), log_key(32), log_sel(32)] + b_func
        float part = Wf[8 + k] * lk + Wf[40 + k] * ls;
        if (k < 8) part += Wf[k] * logf(s_top8[k]);
        float sim = warp_sum(part) + bf[0];

        float lam   = 1.0f / (1.0f + expf(sim - l0));   // softmax([l0,sim])[0]
        float tempe = 1.0f / (1.0f + expf(-l1));        // sigmoid(l1)

        // probs = softmax(-dists*tempe + noise) over K
        float logit = -d * tempe + nz;
        float mx = warp_max(logit);
        float e  = expf(logit - mx);
        float se = warp_sum(e);
        s_p[k] = e / se;
        __syncwarp();

        if (k == 0) {
            out[(size_t)Vdim * ROWS + row] = lam;
            float* orow = out + (size_t)row * Vdim;
            for (int i = 0; i < Kdim; i++) orow[s_t[i]] = s_p[i];  // last-write-wins
        }
    }
}

extern "C" void kernel_launch(void* const* d_in, const int* in_sizes, int n_in,
                              void* d_out, int out_size) {
    const int*   tgt    = (const int*)  d_in[0];
    const float* dists  = (const float*)d_in[1];
    const float* keyf   = (const float*)d_in[2];
    const float* nprobs = (const float*)d_in[3];
    const float* selp   = (const float*)d_in[4];
    const float* Wf     = (const float*)d_in[5];
    const float* bf     = (const float*)d_in[6];
    const float* W1a    = (const float*)d_in[7];
    const float* b1a    = (const float*)d_in[8];
    const float* W1b    = (const float*)d_in[9];
    const float* b1b    = (const float*)d_in[10];
    const float* W2a    = (const float*)d_in[11];
    const float* b2a    = (const float*)d_in[12];
    const float* W2b    = (const float*)d_in[13];
    const float* b2b    = (const float*)d_in[14];
    float* out = (float*)d_out;

    robust_combiner_kernel<<<ROWS, NTHREADS>>>(
        tgt, dists, keyf, nprobs, selp,
        Wf, bf, W1a, b1a, W1b, b1b, W2a, b2a, W2b, b2b, out);
}

// round 11
// speedup vs baseline: 1.9025x; 1.1075x over previous
#include <cuda_runtime.h>
#include <math.h>

#define Bdim 4
#define Sdim 512
#define Kdim 32
#define Vdim 32000
#define ROWS (Bdim * Sdim)   /* 2048 */
#define NTHREADS 256
#define V4 (Vdim / 4)        /* 8000 */
#define CAND_CAP 1024
#define BATCH_END 7168       /* 7 * NTHREADS * 4; tail = 832 float4s */

__device__ __forceinline__ float warp_sum(float v) {
#pragma unroll
    for (int o = 16; o > 0; o >>= 1) v += __shfl_xor_sync(0xffffffffu, v, o);
    return v;
}
__device__ __forceinline__ float warp_max(float v) {
#pragma unroll
    for (int o = 16; o > 0; o >>= 1) v = fmaxf(v, __shfl_xor_sync(0xffffffffu, v, o));
    return v;
}
__device__ __forceinline__ float max4(float4 v) {
    return fmaxf(fmaxf(v.x, v.y), fmaxf(v.z, v.w));
}
// fallback-only: insert into descending 8-list
__device__ __forceinline__ void ins8(float (&t)[8], float v) {
    if (v <= t[7]) return;
    t[7] = v;
#pragma unroll
    for (int i = 7; i > 0; --i)
        if (t[i] > t[i - 1]) { float tmp = t[i - 1]; t[i - 1] = t[i]; t[i] = tmp; }
}
// rare hit path: ONE atomic per hit lane, then sequential stores
__device__ __forceinline__ void collect(float4 v, float T, float* s_cand, int* s_cnt_c) {
    int n = (v.x >= T) + (v.y >= T) + (v.z >= T) + (v.w >= T);
    int p = atomicAdd(s_cnt_c, n);
    if (v.x >= T) { if (p < CAND_CAP) s_cand[p] = v.x; p++; }
    if (v.y >= T) { if (p < CAND_CAP) s_cand[p] = v.y; p++; }
    if (v.z >= T) { if (p < CAND_CAP) s_cand[p] = v.z; p++; }
    if (v.w >= T) { if (p < CAND_CAP) s_cand[p] = v.w; p++; }
}

__global__ __launch_bounds__(NTHREADS, 8)   /* cap regs at 32 -> 8 CTAs/SM */
void robust_combiner_kernel(const int*   __restrict__ tgt,
                            const float* __restrict__ dists,
                            const float* __restrict__ keyf,
                            const float* __restrict__ nprobs,
                            const float* __restrict__ selp,
                            const float* __restrict__ Wf,  const float* __restrict__ bf,
                            const float* __restrict__ W1a, const float* __restrict__ b1a,
                            const float* __restrict__ W1b, const float* __restrict__ b1b,
                            const float* __restrict__ W2a, const float* __restrict__ b2a,
                            const float* __restrict__ W2b, const float* __restrict__ b2b,
                            float* __restrict__ out)
{
    const int row = blockIdx.x;
    const int tid = threadIdx.x;

    __shared__ float s_max[NTHREADS];
    __shared__ float s_cand[CAND_CAP];
    __shared__ int   s_cnt_c;
    __shared__ float s_T;
    __shared__ float s_top8[8];
    __shared__ float s_d[Kdim], s_lk[Kdim], s_ls[Kdim], s_cnt[Kdim], s_p[Kdim];
    __shared__ int   s_t[Kdim];

    const float4* __restrict__ in4  = reinterpret_cast<const float4*>(nprobs) + (size_t)row * V4;
    float4*       __restrict__ out4 = reinterpret_cast<float4*>(out)          + (size_t)row * V4;
    const float4 z4 = make_float4(0.f, 0.f, 0.f, 0.f);
    const size_t kbase = (size_t)row * Kdim;

    if (tid == 0) s_cnt_c = 0;

    // ---- Phase 0: 4096-element subset sample (4 float4 / thread) ----
    // Tighter T -> ~62 expected candidates -> collect path nearly never taken.
    {
        float4 a = in4[tid];
        float4 b = in4[tid + NTHREADS];
        float4 c = in4[tid + 2 * NTHREADS];
        float4 d = in4[tid + 3 * NTHREADS];
        s_max[tid] = fmaxf(fmaxf(max4(a), max4(b)), fmaxf(max4(c), max4(d)));
    }
    __syncthreads();

    // ---- Concurrent: warp 0 threshold; warps 1-4 prefetch phase-C inputs ----
    if (tid < 32) {
        // T = 8th-largest of 256 thread maxima (each a real row element)
        // -> >= 8 row elements >= T -> all global top-8 >= T, cnt >= 8.
        float m8[8];
#pragma unroll
        for (int j = 0; j < 8; j++) m8[j] = s_max[tid + 32 * j];
        float T = 0.f;
#pragma unroll
        for (int r = 0; r < 8; r++) {
            float lv = m8[0]; int lj = 0;
#pragma unroll
            for (int j = 1; j < 8; j++) if (m8[j] > lv) { lv = m8[j]; lj = j; }
            float mv = warp_max(lv);
            unsigned ball = __ballot_sync(0xffffffffu, lv == mv);
            int wl = __ffs(ball) - 1;              // exactly one winner, even on ties
            if (tid == wl) m8[lj] = -INFINITY;
            T = mv;
        }
        if (tid == 0) s_T = T;
    } else if (tid < 64) {
        int j = tid - 32;  s_t[j]  = tgt[kbase + j];
    } else if (tid < 96) {
        int j = tid - 64;  s_d[j]  = dists[kbase + j];
    } else if (tid < 128) {
        int j = tid - 96;  s_lk[j] = logf(keyf[kbase + j]);
    } else if (tid < 160) {
        int j = tid - 128; s_ls[j] = logf(selp[kbase + j]);
    }
    __syncthreads();

    // ---- Main pass: single full DRAM read + zero-fill + rare candidate hits ----
    const float T = s_T;
    for (int base = tid; base < BATCH_END; base += NTHREADS * 4) {
        // 4 loads back-to-back (MLP=4), then 4 stores, then cheap checks
        float4 v0 = __ldcs(&in4[base]);
        float4 v1 = __ldcs(&in4[base +     NTHREADS]);
        float4 v2 = __ldcs(&in4[base + 2 * NTHREADS]);
        float4 v3 = __ldcs(&in4[base + 3 * NTHREADS]);
        __stcs(&out4[base],                z4);
        __stcs(&out4[base +     NTHREADS], z4);
        __stcs(&out4[base + 2 * NTHREADS], z4);
        __stcs(&out4[base + 3 * NTHREADS], z4);
        if (max4(v0) >= T) collect(v0, T, s_cand, &s_cnt_c);
        if (max4(v1) >= T) collect(v1, T, s_cand, &s_cnt_c);
        if (max4(v2) >= T) collect(v2, T, s_cand, &s_cnt_c);
        if (max4(v3) >= T) collect(v3, T, s_cand, &s_cnt_c);
    }
    for (int i = BATCH_END + tid; i < V4; i += NTHREADS) {   // tail: 832 float4s
        float4 v = __ldcs(&in4[i]);
        __stcs(&out4[i], z4);
        if (max4(v) >= T) collect(v, T, s_cand, &s_cnt_c);
    }
    __syncthreads();

    // ---- Exact top-8 from candidates (warp 0); serial fallback on overflow ----
    if (tid < 32) {
        int cnt = s_cnt_c;
        if (cnt <= CAND_CAP) {                     // normal path; cnt >= 8 guaranteed
            int per = (cnt + 31) / 32;             // disjoint lane subsets
#pragma unroll 1
            for (int r = 0; r < 8; r++) {
                float lv = -INFINITY; int li = 0;
                for (int e = 0; e < per; e++) {
                    int idx = tid + 32 * e;
                    if (idx < cnt) { float c = s_cand[idx]; if (c > lv) { lv = c; li = idx; } }
                }
                float mv = warp_max(lv);
                unsigned ball = __ballot_sync(0xffffffffu, lv == mv);
                int wl = __ffs(ball) - 1;          // one removal/round; ties land in
                if (tid == wl) s_cand[li] = -INFINITY;  // consecutive rounds (= top_k)
                if (tid == 0) s_top8[r] = mv;
            }
        } else if (tid == 0) {                     // overflow fallback: serial exact
            float t8[8];
#pragma unroll
            for (int j = 0; j < 8; j++) t8[j] = -1.0f;
            const float* rowp = nprobs + (size_t)row * Vdim;
            for (int i = 0; i < Vdim; i++) ins8(t8, rowp[i]);
#pragma unroll
            for (int j = 0; j < 8; j++) s_top8[j] = t8[j];
        }
    }
    __syncthreads();

    // ---- Phase C: per-row scalar math on warp 0 (one lane per k), inputs smem-hot ----
    if (tid < Kdim) {
        const int k = tid;
        int   tv = s_t[k];
        float d  = s_d[k];
        float lk = s_lk[k];
        float ls = s_ls[k];

        // noise_logit: Linear(2->4) -> tanh -> Linear(4->1)
        float nz = b1b[0];
#pragma unroll
        for (int i = 0; i < 4; i++) {
            float h = tanhf(W1a[2 * i] * lk + W1a[2 * i + 1] * ls + b1a[i]);
            nz += W1b[i] * h;
        }

        // label_counts[k] = # distinct NONZERO labels in prefix [0..k]
        // contrib[i] = (label!=0 && first occurrence); inclusive prefix via ballot+popc
        bool dup = false;
        for (int j = 0; j < k; j++) dup |= (s_t[j] == tv);
        int contrib = (tv != 0) && !dup;
        unsigned ball = __ballot_sync(0xffffffffu, contrib);
        unsigned lemask = 0xffffffffu >> (31 - k);
        s_cnt[k] = (float)__popc(ball & lemask);
        __syncwarp();

        // fc2 hidden unit k: tanh(W2a[k] . [dists(32), counts(32)] + b2a[k])
        float acc = b2a[k];
        const float* wrow = W2a + k * (2 * Kdim);
#pragma unroll
        for (int i = 0; i < Kdim; i++) acc += wrow[i] * s_d[i];
#pragma unroll
        for (int i = 0; i < Kdim; i++) acc += wrow[Kdim + i] * s_cnt[i];
        float h = tanhf(acc);

        // lambda_logit = W2b @ h + b2b
        float l0 = warp_sum(W2b[k] * h)        + b2b[0];
        float l1 = warp_sum(W2b[Kdim + k] * h) + b2b[1];

        // sim_lambda = W_func . [log(top8)(8), log_key(32), log_sel(32)] + b_func
        float part = Wf[8 + k] * lk + Wf[40 + k] * ls;
        if (k < 8) part += Wf[k] * logf(s_top8[k]);
        float sim = warp_sum(part) + bf[0];

        float lam   = 1.0f / (1.0f + expf(sim - l0));   // softmax([l0,sim])[0]
        float tempe = 1.0f / (1.0f + expf(-l1));        // sigmoid(l1)

        // probs = softmax(-dists*tempe + noise) over K
        float logit = -d * tempe + nz;
        float mx = warp_max(logit);
        float e  = expf(logit - mx);
        float se = warp_sum(e);
        s_p[k] = e / se;
        __syncwarp();

        if (k == 0) {
            out[(size_t)Vdim * ROWS + row] = lam;
            float* orow = out + (size_t)row * Vdim;
            for (int i = 0; i < Kdim; i++) orow[s_t[i]] = s_p[i];  // last-write-wins
        }
    }
}

extern "C" void kernel_launch(void* const* d_in, const int* in_sizes, int n_in,
                              void* d_out, int out_size) {
    const int*   tgt    = (const int*)  d_in[0];
    const float* dists  = (const float*)d_in[1];
    const float* keyf   = (const float*)d_in[2];
    const float* nprobs = (const float*)d_in[3];
    const float* selp   = (const float*)d_in[4];
    const float* Wf     = (const float*)d_in[5];
    const float* bf     = (const float*)d_in[6];
    const float* W1a    = (const float*)d_in[7];
    const float* b1a    = (const float*)d_in[8];
    const float* W1b    = (const float*)d_in[9];
    const float* b1b    = (const float*)d_in[10];
    const float* W2a    = (const float*)d_in[11];
    const float* b2a    = (const float*)d_in[12];
    const float* W2b    = (const float*)d_in[13];
    const float* b2b    = (const float*)d_in[14];
    float* out = (float*)d_out;

    robust_combiner_kernel<<<ROWS, NTHREADS>>>(
        tgt, dists, keyf, nprobs, selp,
        Wf, bf, W1a, b1a, W1b, b1b, W2a, b2a, W2b, b2b, out);
}